// round 11
// baseline (speedup 1.0000x reference)
#include <cuda_runtime.h>
#include <cuda_bf16.h>
#include <stdint.h>
#include <math.h>

#define N_ROUTES 7
#define PC_DIM   512
#define MC_DIM   128
#define KCLS     25
#define BSZ      4096
#define COLS     (KCLS * MC_DIM)        // 3200
#define VOTE_PER_B (N_ROUTES * COLS)    // 22400
#define PP_STRIDE (N_ROUTES * PC_DIM)   // 3584
#define NCHUNK_B 4
#define CHUNK_ROWS (BSZ / NCHUNK_B)     // 1024

__device__ float g_vote[(size_t)BSZ * VOTE_PER_B];                    // 367 MB
__device__ __nv_bfloat16 g_Phi[(size_t)BSZ * PP_STRIDE];
__device__ __nv_bfloat16 g_Plo[(size_t)BSZ * PP_STRIDE];
__device__ __nv_bfloat16 g_Whi[(size_t)N_ROUTES * COLS * PC_DIM];     // [n][col][d]
__device__ __nv_bfloat16 g_Wlo[(size_t)N_ROUTES * COLS * PC_DIM];

__device__ __forceinline__ uint32_t smem_to_u32(const void* p) {
    uint32_t a;
    asm("{ .reg .u64 t; cvta.to.shared.u64 t, %1; cvt.u32.u64 %0, t; }"
        : "=r"(a) : "l"(p));
    return a;
}
__device__ __forceinline__ uint32_t usw64(uint32_t o) {     // SW64 swizzle
    return o ^ ((o >> 3) & 0x30);
}

#define CP_ASYNC(sa, ga) \
    asm volatile("cp.async.cg.shared.global [%0], [%1], 16;" :: "r"(sa), "l"(ga))
#define CP_COMMIT() asm volatile("cp.async.commit_group;" ::: "memory")
#define CP_WAIT(N)  asm volatile("cp.async.wait_group %0;" :: "n"(N))

// ---------------------------------------------------------------------------
// Prep 1: split prim_pose into bf16 hi/lo
// ---------------------------------------------------------------------------
__global__ __launch_bounds__(512) void prep_p_kernel(const float* __restrict__ P) {
    size_t i = (size_t)blockIdx.x * 512 + threadIdx.x;   // float4 index
    float4 x = ((const float4*)P)[i];
    __nv_bfloat16 h0 = __float2bfloat16(x.x);
    __nv_bfloat16 h1 = __float2bfloat16(x.y);
    __nv_bfloat16 h2 = __float2bfloat16(x.z);
    __nv_bfloat16 h3 = __float2bfloat16(x.w);
    __nv_bfloat162* dh = (__nv_bfloat162*)g_Phi;
    __nv_bfloat162* dl = (__nv_bfloat162*)g_Plo;
    dh[2 * i]     = __nv_bfloat162(h0, h1);
    dh[2 * i + 1] = __nv_bfloat162(h2, h3);
    dl[2 * i] = __nv_bfloat162(__float2bfloat16(x.x - __bfloat162float(h0)),
                               __float2bfloat16(x.y - __bfloat162float(h1)));
    dl[2 * i + 1] = __nv_bfloat162(__float2bfloat16(x.z - __bfloat162float(h2)),
                                   __float2bfloat16(x.w - __bfloat162float(h3)));
}

// ---------------------------------------------------------------------------
// Prep 2: transpose+split W[n][d][col] -> Whi/Wlo [n][col][d]
// ---------------------------------------------------------------------------
__global__ __launch_bounds__(256) void prep_w_kernel(const float* __restrict__ W) {
    __shared__ float tile[32][33];
    const int n = blockIdx.z;
    const int c0 = blockIdx.x * 32;
    const int d0 = blockIdx.y * 32;
    const float* Wn = W + (size_t)n * PC_DIM * COLS;
#pragma unroll
    for (int j = 0; j < 4; j++) {
        int d = d0 + threadIdx.y + j * 8;
        tile[threadIdx.y + j * 8][threadIdx.x] = Wn[(size_t)d * COLS + c0 + threadIdx.x];
    }
    __syncthreads();
#pragma unroll
    for (int j = 0; j < 4; j++) {
        int col = c0 + threadIdx.y + j * 8;
        int d = d0 + threadIdx.x;
        float x = tile[threadIdx.x][threadIdx.y + j * 8];
        __nv_bfloat16 h = __float2bfloat16(x);
        size_t o = ((size_t)n * COLS + col) * PC_DIM + d;
        g_Whi[o] = h;
        g_Wlo[o] = __float2bfloat16(x - __bfloat162float(h));
    }
}

// ---------------------------------------------------------------------------
// Vote GEMM (R5 core): mma.sync bf16 3-term split. CTA 128x128, 8 warps
// (4 wm x 2 wn, warp tile 32x64). KCH=32, SW64 smem, 3-stage cp.async.
// bm_base selects the batch chunk.
// ---------------------------------------------------------------------------
#define KCH 32
#define T_AH 0
#define T_AL 8192
#define T_BH 16384
#define T_BL 24576
#define STG_BYTES 32768
#define NSTG 3
#define GEMM_SMEM (NSTG * STG_BYTES)      // 98304 -> 2 CTAs/SM
#define NC (PC_DIM / KCH)                 // 16

#define LDSM_X4(r0, r1, r2, r3, a) \
    asm volatile("ldmatrix.sync.aligned.m8n8.x4.shared.b16 {%0,%1,%2,%3}, [%4];" \
        : "=r"(r0), "=r"(r1), "=r"(r2), "=r"(r3) : "r"(a))

#define MMA_BF16(d, a, b0, b1) \
    asm volatile("mma.sync.aligned.m16n8k16.row.col.f32.bf16.bf16.f32 " \
        "{%0,%1,%2,%3}, {%4,%5,%6,%7}, {%8,%9}, {%0,%1,%2,%3};" \
        : "+f"((d)[0]), "+f"((d)[1]), "+f"((d)[2]), "+f"((d)[3]) \
        : "r"((a)[0]), "r"((a)[1]), "r"((a)[2]), "r"((a)[3]), "r"(b0), "r"(b1))

__global__ __launch_bounds__(256, 2) void vote_gemm_tc(int bm_base) {
    extern __shared__ char smem[];
    const uint32_t sb = smem_to_u32(smem);
    const int tid  = threadIdx.x;
    const int lane = tid & 31;
    const int warp = tid >> 5;
    const int wm   = warp & 3;          // M block of 32
    const int wn   = warp >> 2;         // N block of 64

    const int n  = blockIdx.z;
    const int bm = bm_base + blockIdx.y * 128;
    const int bn = blockIdx.x * 128;

    const __nv_bfloat16* Ahi = g_Phi + (size_t)bm * PP_STRIDE + (size_t)n * PC_DIM;
    const __nv_bfloat16* Alo = g_Plo + (size_t)bm * PP_STRIDE + (size_t)n * PC_DIM;
    const __nv_bfloat16* Bhi = g_Whi + ((size_t)n * COLS + bn) * PC_DIM;
    const __nv_bfloat16* Blo = g_Wlo + ((size_t)n * COLS + bn) * PC_DIM;

    float acc[2][8][4];
#pragma unroll
    for (int i = 0; i < 2; i++)
#pragma unroll
        for (int j = 0; j < 8; j++)
#pragma unroll
            for (int q = 0; q < 4; q++) acc[i][j][q] = 0.f;

    const int lrow = lane & 15, lch = lane >> 4;

    auto issue_stage = [&](int c, int buf) {
        const int k0 = c * KCH;
        const uint32_t sbase = sb + buf * STG_BYTES;
#pragma unroll
        for (int p = 0; p < 8; p++) {
            int id  = p * 256 + tid;
            int t   = id >> 9;          // 0..3
            int rem = id & 511;
            int row = rem >> 2;
            int ch  = rem & 3;
            uint32_t sa = sbase + t * 8192 + usw64(row * 64 + ch * 16);
            const __nv_bfloat16* g;
            if (t == 0)      g = Ahi + (size_t)row * PP_STRIDE + k0 + ch * 8;
            else if (t == 1) g = Alo + (size_t)row * PP_STRIDE + k0 + ch * 8;
            else if (t == 2) g = Bhi + (size_t)row * PC_DIM + k0 + ch * 8;
            else             g = Blo + (size_t)row * PC_DIM + k0 + ch * 8;
            CP_ASYNC(sa, g);
        }
        CP_COMMIT();
    };

    issue_stage(0, 0);
    issue_stage(1, 1);
    issue_stage(2, 2);

    for (int c = 0; c < NC; c++) {
        if (c <= NC - 3)      CP_WAIT(2);
        else if (c == NC - 2) CP_WAIT(1);
        else                  CP_WAIT(0);
        __syncthreads();

        const uint32_t sbase = sb + (c % 3) * STG_BYTES;
#pragma unroll
        for (int ks = 0; ks < 2; ks++) {
            const uint32_t kb = ks * 32 + lch * 16;
            uint32_t ah[2][4], al[2][4];
#pragma unroll
            for (int mt = 0; mt < 2; mt++) {
                uint32_t ao = usw64((wm * 32 + mt * 16 + lrow) * 64 + kb);
                LDSM_X4(ah[mt][0], ah[mt][1], ah[mt][2], ah[mt][3], sbase + T_AH + ao);
                LDSM_X4(al[mt][0], al[mt][1], al[mt][2], al[mt][3], sbase + T_AL + ao);
            }
#pragma unroll
            for (int g = 0; g < 4; g++) {
                uint32_t bo = usw64((wn * 64 + g * 16 + lrow) * 64 + kb);
                uint32_t bh[4], bl[4];
                LDSM_X4(bh[0], bh[1], bh[2], bh[3], sbase + T_BH + bo);
                LDSM_X4(bl[0], bl[1], bl[2], bl[3], sbase + T_BL + bo);
                MMA_BF16(acc[0][g * 2 + 0], ah[0], bh[0], bh[2]);
                MMA_BF16(acc[0][g * 2 + 1], ah[0], bh[1], bh[3]);
                MMA_BF16(acc[1][g * 2 + 0], ah[1], bh[0], bh[2]);
                MMA_BF16(acc[1][g * 2 + 1], ah[1], bh[1], bh[3]);
                MMA_BF16(acc[0][g * 2 + 0], ah[0], bl[0], bl[2]);
                MMA_BF16(acc[0][g * 2 + 1], ah[0], bl[1], bl[3]);
                MMA_BF16(acc[1][g * 2 + 0], ah[1], bl[0], bl[2]);
                MMA_BF16(acc[1][g * 2 + 1], ah[1], bl[1], bl[3]);
                MMA_BF16(acc[0][g * 2 + 0], al[0], bh[0], bh[2]);
                MMA_BF16(acc[0][g * 2 + 1], al[0], bh[1], bh[3]);
                MMA_BF16(acc[1][g * 2 + 0], al[1], bh[0], bh[2]);
                MMA_BF16(acc[1][g * 2 + 1], al[1], bh[1], bh[3]);
            }
        }
        __syncthreads();
        if (c + 3 < NC) issue_stage(c + 3, (c + 3) % 3);
    }

    // epilogue: direct fp32 stores
#pragma unroll
    for (int mt = 0; mt < 2; mt++) {
#pragma unroll
        for (int j = 0; j < 8; j++) {
            int g = j >> 1, nt = j & 1;
            int row = bm + wm * 32 + mt * 16 + (lane >> 2);
            int col = bn + wn * 64 + g * 16 + nt * 8 + (lane & 3) * 2;
            float* d0 = g_vote + (size_t)row * VOTE_PER_B + (size_t)n * COLS + col;
            float* d1 = d0 + (size_t)8 * VOTE_PER_B;
            *(float2*)d0 = make_float2(acc[mt][j][0], acc[mt][j][1]);
            *(float2*)d1 = make_float2(acc[mt][j][2], acc[mt][j][3]);
        }
    }
}

// ---------------------------------------------------------------------------
// Persistent routing over a row range [r0, r1): 296 CTAs, 800 threads
// (25 warps, warp = capsule m). Double-buffered cp.async vote prefetch.
// ---------------------------------------------------------------------------
#define ROUT_GRID 296
#define ROW_FLOATS VOTE_PER_B                    // 22400
#define ROUT_SMEM (2 * ROW_FLOATS * 4)           // 179200 bytes

__device__ __forceinline__ float warp_sum(float v) {
#pragma unroll
    for (int o = 16; o; o >>= 1) v += __shfl_xor_sync(0xffffffffu, v, o);
    return v;
}
__device__ __forceinline__ float warp_max32(float v) {
#pragma unroll
    for (int o = 16; o; o >>= 1) v = fmaxf(v, __shfl_xor_sync(0xffffffffu, v, o));
    return v;
}
__device__ __forceinline__ void warp_sum2(float& a, float& b) {
#pragma unroll
    for (int o = 16; o; o >>= 1) {
        a += __shfl_xor_sync(0xffffffffu, a, o);
        b += __shfl_xor_sync(0xffffffffu, b, o);
    }
}

__global__ __launch_bounds__(800, 1) void routing_kernel(
    const float* __restrict__ prim_act,
    const float* __restrict__ ln_gamma, const float* __restrict__ ln_beta,
    const float* __restrict__ embedding, const float* __restrict__ bias,
    float* __restrict__ out_logits, float* __restrict__ out_act,
    float* __restrict__ out_coef, int r0, int r1) {
    extern __shared__ float s_vote[];            // 2 x 22400 floats
    __shared__ float s_agree[N_ROUTES * KCLS];
    __shared__ float s_coef[N_ROUTES * KCLS];

    const int tid  = threadIdx.x;
    const int lane = tid & 31;
    const int m    = tid >> 5;                   // warp id == capsule, 0..24
    const uint32_t sb = smem_to_u32(s_vote);

    const float4 g4 = ((const float4*)ln_gamma)[lane];
    const float4 b4 = ((const float4*)ln_beta)[lane];
    const float4 em = ((const float4*)(embedding + (size_t)m * MC_DIM))[lane];
    const float  bi = bias[m];

    auto prefetch = [&](int row, int buf) {
        const float4* src = (const float4*)(g_vote + (size_t)row * VOTE_PER_B);
        const uint32_t dst = sb + buf * (ROW_FLOATS * 4);
#pragma unroll
        for (int j = 0; j < 7; j++) {
            int idx = tid + j * 800;             // 5600 float4 total
            CP_ASYNC(dst + idx * 16, src + idx);
        }
        CP_COMMIT();
    };

    if (r0 + (int)blockIdx.x < r1) prefetch(r0 + blockIdx.x, 0);
    int buf = 0;

    for (int r = r0 + blockIdx.x; r < r1; r += ROUT_GRID) {
        if (r + ROUT_GRID < r1) {
            prefetch(r + ROUT_GRID, buf ^ 1);
            CP_WAIT(1);
        } else {
            CP_WAIT(0);
        }
        __syncthreads();

        float a_r[N_ROUTES];
#pragma unroll
        for (int nn = 0; nn < N_ROUTES; nn++)
            a_r[nn] = prim_act[(size_t)r * N_ROUTES + nn];

        float4 v[N_ROUTES];
        {
            const float* vb = s_vote + buf * ROW_FLOATS + m * MC_DIM + lane * 4;
#pragma unroll
            for (int nn = 0; nn < N_ROUTES; nn++)
                v[nn] = *(const float4*)(vb + nn * COLS);
        }

        float4 p = make_float4(0.f, 0.f, 0.f, 0.f);
#pragma unroll
        for (int nn = 0; nn < N_ROUTES; nn++) {
            p.x += a_r[nn] * v[nn].x;
            p.y += a_r[nn] * v[nn].y;
            p.z += a_r[nn] * v[nn].z;
            p.w += a_r[nn] * v[nn].w;
        }
        p.x *= (1.f / 25.f); p.y *= (1.f / 25.f);
        p.z *= (1.f / 25.f); p.w *= (1.f / 25.f);

        auto layernorm = [&](float4& x) {
            float s1 = x.x + x.y + x.z + x.w;
            float s2 = x.x * x.x + x.y * x.y + x.z * x.z + x.w * x.w;
            warp_sum2(s1, s2);
            float mu = s1 * (1.f / MC_DIM);
            float ve = s2 * (1.f / MC_DIM) - mu * mu + 1e-5f;
            float rr = rsqrtf(ve);
            rr = rr * (1.5f - 0.5f * ve * rr * rr);
            x.x = (x.x - mu) * rr * g4.x + b4.x;
            x.y = (x.y - mu) * rr * g4.y + b4.y;
            x.z = (x.z - mu) * rr * g4.z + b4.z;
            x.w = (x.w - mu) * rr * g4.w + b4.w;
        };
        layernorm(p);

        const float scale = 0.08838834764831845f;   // 1/sqrt(128)
#pragma unroll
        for (int it = 1; it <= 2; it++) {
#pragma unroll
            for (int nn = 0; nn < N_ROUTES; nn++) {
                float d = v[nn].x * p.x + v[nn].y * p.y + v[nn].z * p.z + v[nn].w * p.w;
                d = warp_sum(d);
                if (lane == 0) s_agree[nn * KCLS + m] = d * scale;
            }
            __syncthreads();

            if (m < N_ROUTES) {
                float aval = (lane < KCLS) ? s_agree[m * KCLS + lane] : -1e30f;
                float mx = warp_max32(aval);
                float e = (lane < KCLS) ? expf(aval - mx) : 0.f;
                float s = warp_sum(e);
                if (lane < KCLS) s_coef[m * KCLS + lane] = e / s;
            }
            __syncthreads();

            if (it == 2 && tid < N_ROUTES * KCLS)
                out_coef[(size_t)r * (N_ROUTES * KCLS) + tid] = s_coef[tid];

            p = make_float4(0.f, 0.f, 0.f, 0.f);
#pragma unroll
            for (int nn = 0; nn < N_ROUTES; nn++) {
                float ca = s_coef[nn * KCLS + m] * a_r[nn];
                p.x += ca * v[nn].x;
                p.y += ca * v[nn].y;
                p.z += ca * v[nn].z;
                p.w += ca * v[nn].w;
            }
            layernorm(p);
            __syncthreads();
        }

        {
            float d = p.x * em.x + p.y * em.y + p.z * em.z + p.w * em.w;
            d = warp_sum(d);
            if (lane == 0) out_logits[(size_t)r * KCLS + m] = d + bi;
        }
        if (tid < N_ROUTES)
            out_act[(size_t)r * N_ROUTES + tid] = a_r[tid];

        buf ^= 1;
        __syncthreads();
    }
}

// ---------------------------------------------------------------------------
// Launch: chunked GEMM (stream 0) overlapped with routing (high-prio stream),
// joined with events so the whole thing stays a single capturable graph.
// ---------------------------------------------------------------------------
extern "C" void kernel_launch(void* const* d_in, const int* in_sizes, int n_in,
                              void* d_out, int out_size) {
    const float* prim_pose = (const float*)d_in[0];
    const float* prim_act  = (const float*)d_in[1];
    const float* w         = (const float*)d_in[2];
    const float* ln_gamma  = (const float*)d_in[3];
    const float* ln_beta   = (const float*)d_in[4];
    const float* embedding = (const float*)d_in[5];
    const float* bias      = (const float*)d_in[6];

    float* out        = (float*)d_out;
    float* out_logits = out;
    float* out_act    = out + (size_t)BSZ * KCLS;
    float* out_coef   = out_act + (size_t)BSZ * N_ROUTES;

    // one-time handle creation (first call is the uncaptured correctness run)
    static cudaStream_t s1 = nullptr;
    static cudaEvent_t evRoot, evP, evDone;
    static cudaEvent_t evG[NCHUNK_B];
    if (s1 == nullptr) {
        int lo, hi;
        cudaDeviceGetStreamPriorityRange(&lo, &hi);
        cudaStreamCreateWithPriority(&s1, cudaStreamNonBlocking, hi);
        cudaEventCreateWithFlags(&evRoot, cudaEventDisableTiming);
        cudaEventCreateWithFlags(&evP, cudaEventDisableTiming);
        cudaEventCreateWithFlags(&evDone, cudaEventDisableTiming);
        for (int i = 0; i < NCHUNK_B; i++)
            cudaEventCreateWithFlags(&evG[i], cudaEventDisableTiming);
        cudaFuncSetAttribute(vote_gemm_tc,
                             cudaFuncAttributeMaxDynamicSharedMemorySize, GEMM_SMEM);
        cudaFuncSetAttribute(routing_kernel,
                             cudaFuncAttributeMaxDynamicSharedMemorySize, ROUT_SMEM);
    }

    // fork s1 from the (capture-origin) default stream
    cudaEventRecord(evRoot, 0);
    cudaStreamWaitEvent(s1, evRoot, 0);

    // preps in parallel: prep_w on stream 0, prep_p on s1
    prep_w_kernel<<<dim3(COLS / 32, PC_DIM / 32, N_ROUTES), dim3(32, 8), 0, 0>>>(w);
    prep_p_kernel<<<(BSZ * PP_STRIDE) / 4 / 512, 512, 0, s1>>>(prim_pose);
    cudaEventRecord(evP, s1);
    cudaStreamWaitEvent(0, evP, 0);

    // chunked GEMM on stream 0; routing for chunk c on s1 after gemm chunk c
    for (int c = 0; c < NCHUNK_B; c++) {
        dim3 g(COLS / 128, CHUNK_ROWS / 128, N_ROUTES);   // (25, 8, 7)
        vote_gemm_tc<<<g, 256, GEMM_SMEM, 0>>>(c * CHUNK_ROWS);
        cudaEventRecord(evG[c], 0);
        cudaStreamWaitEvent(s1, evG[c], 0);
        routing_kernel<<<ROUT_GRID, 800, ROUT_SMEM, s1>>>(
            prim_act, ln_gamma, ln_beta, embedding, bias,
            out_logits, out_act, out_coef,
            c * CHUNK_ROWS, (c + 1) * CHUNK_ROWS);
    }

    // rejoin
    cudaEventRecord(evDone, s1);
    cudaStreamWaitEvent(0, evDone, 0);
}

// round 12
// speedup vs baseline: 1.0532x; 1.0532x over previous
#include <cuda_runtime.h>
#include <cuda_fp16.h>
#include <stdint.h>
#include <math.h>

#define N_ROUTES 7
#define PC_DIM   512
#define MC_DIM   128
#define KCLS     25
#define BSZ      4096
#define COLS     (KCLS * MC_DIM)        // 3200
#define VOTE_PER_B (N_ROUTES * COLS)    // 22400
#define PP_STRIDE (N_ROUTES * PC_DIM)   // 3584

__device__ float g_vote[(size_t)BSZ * VOTE_PER_B];                    // 367 MB
__device__ __half g_Phi[(size_t)BSZ * PP_STRIDE];
__device__ __half g_Plo[(size_t)BSZ * PP_STRIDE];
__device__ __half g_Whi[(size_t)N_ROUTES * COLS * PC_DIM];            // [n][col][d]
__device__ __half g_Wlo[(size_t)N_ROUTES * COLS * PC_DIM];

__device__ __forceinline__ uint32_t smem_to_u32(const void* p) {
    uint32_t a;
    asm("{ .reg .u64 t; cvta.to.shared.u64 t, %1; cvt.u32.u64 %0, t; }"
        : "=r"(a) : "l"(p));
    return a;
}
__device__ __forceinline__ uint32_t usw64(uint32_t o) {     // SW64 swizzle
    return o ^ ((o >> 3) & 0x30);
}

#define CP_ASYNC(sa, ga) \
    asm volatile("cp.async.cg.shared.global [%0], [%1], 16;" :: "r"(sa), "l"(ga))
#define CP_COMMIT() asm volatile("cp.async.commit_group;" ::: "memory")
#define CP_WAIT(N)  asm volatile("cp.async.wait_group %0;" :: "n"(N))

// ---------------------------------------------------------------------------
// Prep 1: split prim_pose into fp16 hi/lo
// ---------------------------------------------------------------------------
__global__ __launch_bounds__(512) void prep_p_kernel(const float* __restrict__ P) {
    size_t i = (size_t)blockIdx.x * 512 + threadIdx.x;   // float4 index
    float4 x = ((const float4*)P)[i];
    __half h0 = __float2half(x.x), h1 = __float2half(x.y);
    __half h2 = __float2half(x.z), h3 = __float2half(x.w);
    __half2* dh = (__half2*)g_Phi;
    __half2* dl = (__half2*)g_Plo;
    dh[2 * i]     = __halves2half2(h0, h1);
    dh[2 * i + 1] = __halves2half2(h2, h3);
    dl[2 * i]     = __halves2half2(__float2half(x.x - __half2float(h0)),
                                   __float2half(x.y - __half2float(h1)));
    dl[2 * i + 1] = __halves2half2(__float2half(x.z - __half2float(h2)),
                                   __float2half(x.w - __half2float(h3)));
}

// ---------------------------------------------------------------------------
// Prep 2: transpose+split W[n][d][col] -> Whi/Wlo [n][col][d] (fp16)
// ---------------------------------------------------------------------------
__global__ __launch_bounds__(256) void prep_w_kernel(const float* __restrict__ W) {
    __shared__ float tile[32][33];
    const int n = blockIdx.z;
    const int c0 = blockIdx.x * 32;
    const int d0 = blockIdx.y * 32;
    const float* Wn = W + (size_t)n * PC_DIM * COLS;
#pragma unroll
    for (int j = 0; j < 4; j++) {
        int d = d0 + threadIdx.y + j * 8;
        tile[threadIdx.y + j * 8][threadIdx.x] = Wn[(size_t)d * COLS + c0 + threadIdx.x];
    }
    __syncthreads();
#pragma unroll
    for (int j = 0; j < 4; j++) {
        int col = c0 + threadIdx.y + j * 8;
        int d = d0 + threadIdx.x;
        float x = tile[threadIdx.x][threadIdx.y + j * 8];
        __half h = __float2half(x);
        size_t o = ((size_t)n * COLS + col) * PC_DIM + d;
        g_Whi[o] = h;
        g_Wlo[o] = __float2half(x - __half2float(h));
    }
}

// ---------------------------------------------------------------------------
// Vote GEMM: fp16 2-digit split. hh term -> fp32-acc MMA; hl+lh -> shared
// fp16-acc MMA (rate-hypothesis test). CTA 128x128, 512 threads, 16 warps
// (4 wm x 4 wn, warp tile 32x32). KCH=32, SW64 smem, 3-stage cp.async.
// ---------------------------------------------------------------------------
#define KCH 32
#define T_AH 0
#define T_AL 8192
#define T_BH 16384
#define T_BL 24576
#define STG_BYTES 32768
#define NSTG 3
#define GEMM_SMEM (NSTG * STG_BYTES)      // 98304
#define NC (PC_DIM / KCH)                 // 16

#define LDSM_X4(r0, r1, r2, r3, a) \
    asm volatile("ldmatrix.sync.aligned.m8n8.x4.shared.b16 {%0,%1,%2,%3}, [%4];" \
        : "=r"(r0), "=r"(r1), "=r"(r2), "=r"(r3) : "r"(a))

#define MMA_F32ACC(d, a, b0, b1) \
    asm volatile("mma.sync.aligned.m16n8k16.row.col.f32.f16.f16.f32 " \
        "{%0,%1,%2,%3}, {%4,%5,%6,%7}, {%8,%9}, {%0,%1,%2,%3};" \
        : "+f"((d)[0]), "+f"((d)[1]), "+f"((d)[2]), "+f"((d)[3]) \
        : "r"((a)[0]), "r"((a)[1]), "r"((a)[2]), "r"((a)[3]), "r"(b0), "r"(b1))

#define MMA_F16ACC(d, a, b0, b1) \
    asm volatile("mma.sync.aligned.m16n8k16.row.col.f16.f16.f16.f16 " \
        "{%0,%1}, {%2,%3,%4,%5}, {%6,%7}, {%0,%1};" \
        : "+r"((d)[0]), "+r"((d)[1]) \
        : "r"((a)[0]), "r"((a)[1]), "r"((a)[2]), "r"((a)[3]), "r"(b0), "r"(b1))

__global__ __launch_bounds__(512, 1) void vote_gemm_tc(void) {
    extern __shared__ char smem[];
    const uint32_t sb = smem_to_u32(smem);
    const int tid  = threadIdx.x;
    const int lane = tid & 31;
    const int warp = tid >> 5;
    const int wm   = warp & 3;          // M block of 32
    const int wn   = warp >> 2;         // N block of 32 (0..3)

    const int n  = blockIdx.z;
    const int bm = blockIdx.y * 128;
    const int bn = blockIdx.x * 128;

    const __half* Ahi = g_Phi + (size_t)bm * PP_STRIDE + (size_t)n * PC_DIM;
    const __half* Alo = g_Plo + (size_t)bm * PP_STRIDE + (size_t)n * PC_DIM;
    const __half* Bhi = g_Whi + ((size_t)n * COLS + bn) * PC_DIM;
    const __half* Blo = g_Wlo + ((size_t)n * COLS + bn) * PC_DIM;

    float acc[2][4][4];                 // hh term, fp32 accumulate
    uint32_t acch[2][4][2];             // hl+lh terms, fp16 accumulate (half2)
#pragma unroll
    for (int i = 0; i < 2; i++)
#pragma unroll
        for (int j = 0; j < 4; j++) {
#pragma unroll
            for (int q = 0; q < 4; q++) acc[i][j][q] = 0.f;
            acch[i][j][0] = 0u; acch[i][j][1] = 0u;
        }

    const int lrow = lane & 15, lch = lane >> 4;

    auto issue_stage = [&](int c, int buf) {
        const int k0 = c * KCH;
        const uint32_t sbase = sb + buf * STG_BYTES;
#pragma unroll
        for (int p = 0; p < 4; p++) {
            int id  = p * 512 + tid;    // 0..2047
            int t   = id >> 9;          // 0..3
            int rem = id & 511;
            int row = rem >> 2;
            int ch  = rem & 3;
            uint32_t sa = sbase + t * 8192 + usw64(row * 64 + ch * 16);
            const __half* g;
            if (t == 0)      g = Ahi + (size_t)row * PP_STRIDE + k0 + ch * 8;
            else if (t == 1) g = Alo + (size_t)row * PP_STRIDE + k0 + ch * 8;
            else if (t == 2) g = Bhi + (size_t)row * PC_DIM + k0 + ch * 8;
            else             g = Blo + (size_t)row * PC_DIM + k0 + ch * 8;
            CP_ASYNC(sa, g);
        }
        CP_COMMIT();
    };

    issue_stage(0, 0);
    issue_stage(1, 1);
    issue_stage(2, 2);

    for (int c = 0; c < NC; c++) {
        if (c <= NC - 3)      CP_WAIT(2);
        else if (c == NC - 2) CP_WAIT(1);
        else                  CP_WAIT(0);
        __syncthreads();

        const uint32_t sbase = sb + (c % 3) * STG_BYTES;
#pragma unroll
        for (int ks = 0; ks < 2; ks++) {
            const uint32_t kb = ks * 32 + lch * 16;
            uint32_t ah[2][4], al[2][4];
#pragma unroll
            for (int mt = 0; mt < 2; mt++) {
                uint32_t ao = usw64((wm * 32 + mt * 16 + lrow) * 64 + kb);
                LDSM_X4(ah[mt][0], ah[mt][1], ah[mt][2], ah[mt][3], sbase + T_AH + ao);
                LDSM_X4(al[mt][0], al[mt][1], al[mt][2], al[mt][3], sbase + T_AL + ao);
            }
#pragma unroll
            for (int g = 0; g < 2; g++) {
                uint32_t bo = usw64((wn * 32 + g * 16 + lrow) * 64 + kb);
                uint32_t bh[4], bl[4];
                LDSM_X4(bh[0], bh[1], bh[2], bh[3], sbase + T_BH + bo);
                LDSM_X4(bl[0], bl[1], bl[2], bl[3], sbase + T_BL + bo);
#pragma unroll
                for (int mt = 0; mt < 2; mt++) {
                    // hh -> fp32 accumulate
                    MMA_F32ACC(acc[mt][g * 2 + 0], ah[mt], bh[0], bh[2]);
                    MMA_F32ACC(acc[mt][g * 2 + 1], ah[mt], bh[1], bh[3]);
                    // hl + lh -> shared fp16 accumulate
                    MMA_F16ACC(acch[mt][g * 2 + 0], ah[mt], bl[0], bl[2]);
                    MMA_F16ACC(acch[mt][g * 2 + 1], ah[mt], bl[1], bl[3]);
                    MMA_F16ACC(acch[mt][g * 2 + 0], al[mt], bh[0], bh[2]);
                    MMA_F16ACC(acch[mt][g * 2 + 1], al[mt], bh[1], bh[3]);
                }
            }
        }
        __syncthreads();
        if (c + 3 < NC) issue_stage(c + 3, (c + 3) % 3);
    }

    // epilogue: combine fp32 + fp16 accumulators, store fp32
#pragma unroll
    for (int mt = 0; mt < 2; mt++) {
#pragma unroll
        for (int j = 0; j < 4; j++) {
            int g = j >> 1, nt = j & 1;
            int row = bm + wm * 32 + mt * 16 + (lane >> 2);
            int col = bn + wn * 32 + g * 16 + nt * 8 + (lane & 3) * 2;
            float2 x01 = __half22float2(*(__half2*)&acch[mt][j][0]);
            float2 x23 = __half22float2(*(__half2*)&acch[mt][j][1]);
            float* d0 = g_vote + (size_t)row * VOTE_PER_B + (size_t)n * COLS + col;
            float* d1 = d0 + (size_t)8 * VOTE_PER_B;
            *(float2*)d0 = make_float2(acc[mt][j][0] + x01.x, acc[mt][j][1] + x01.y);
            *(float2*)d1 = make_float2(acc[mt][j][2] + x23.x, acc[mt][j][3] + x23.y);
        }
    }
}

// ---------------------------------------------------------------------------
// Persistent routing (R10, best known): 296 CTAs, 800 threads, double-buffered
// cp.async vote prefetch. Warp = capsule m.
// ---------------------------------------------------------------------------
#define ROUT_GRID 296
#define ROW_FLOATS VOTE_PER_B                    // 22400
#define ROUT_SMEM (2 * ROW_FLOATS * 4)           // 179200 bytes

__device__ __forceinline__ float warp_sum(float v) {
#pragma unroll
    for (int o = 16; o; o >>= 1) v += __shfl_xor_sync(0xffffffffu, v, o);
    return v;
}
__device__ __forceinline__ float warp_max32(float v) {
#pragma unroll
    for (int o = 16; o; o >>= 1) v = fmaxf(v, __shfl_xor_sync(0xffffffffu, v, o));
    return v;
}
__device__ __forceinline__ void warp_sum2(float& a, float& b) {
#pragma unroll
    for (int o = 16; o; o >>= 1) {
        a += __shfl_xor_sync(0xffffffffu, a, o);
        b += __shfl_xor_sync(0xffffffffu, b, o);
    }
}

__global__ __launch_bounds__(800, 1) void routing_kernel(
    const float* __restrict__ prim_act,
    const float* __restrict__ ln_gamma, const float* __restrict__ ln_beta,
    const float* __restrict__ embedding, const float* __restrict__ bias,
    float* __restrict__ out_logits, float* __restrict__ out_act,
    float* __restrict__ out_coef) {
    extern __shared__ float s_vote[];            // 2 x 22400 floats
    __shared__ float s_agree[N_ROUTES * KCLS];
    __shared__ float s_coef[N_ROUTES * KCLS];

    const int tid  = threadIdx.x;
    const int lane = tid & 31;
    const int m    = tid >> 5;                   // warp id == capsule, 0..24
    const uint32_t sb = smem_to_u32(s_vote);

    const float4 g4 = ((const float4*)ln_gamma)[lane];
    const float4 b4 = ((const float4*)ln_beta)[lane];
    const float4 em = ((const float4*)(embedding + (size_t)m * MC_DIM))[lane];
    const float  bi = bias[m];

    auto prefetch = [&](int row, int buf) {
        const float4* src = (const float4*)(g_vote + (size_t)row * VOTE_PER_B);
        const uint32_t dst = sb + buf * (ROW_FLOATS * 4);
#pragma unroll
        for (int j = 0; j < 7; j++) {
            int idx = tid + j * 800;             // 5600 float4 total
            CP_ASYNC(dst + idx * 16, src + idx);
        }
        CP_COMMIT();
    };

    prefetch(blockIdx.x, 0);
    int buf = 0;

    for (int r = blockIdx.x; r < BSZ; r += ROUT_GRID) {
        if (r + ROUT_GRID < BSZ) {
            prefetch(r + ROUT_GRID, buf ^ 1);
            CP_WAIT(1);
        } else {
            CP_WAIT(0);
        }
        __syncthreads();

        float a_r[N_ROUTES];
#pragma unroll
        for (int nn = 0; nn < N_ROUTES; nn++)
            a_r[nn] = prim_act[(size_t)r * N_ROUTES + nn];

        float4 v[N_ROUTES];
        {
            const float* vb = s_vote + buf * ROW_FLOATS + m * MC_DIM + lane * 4;
#pragma unroll
            for (int nn = 0; nn < N_ROUTES; nn++)
                v[nn] = *(const float4*)(vb + nn * COLS);
        }

        float4 p = make_float4(0.f, 0.f, 0.f, 0.f);
#pragma unroll
        for (int nn = 0; nn < N_ROUTES; nn++) {
            p.x += a_r[nn] * v[nn].x;
            p.y += a_r[nn] * v[nn].y;
            p.z += a_r[nn] * v[nn].z;
            p.w += a_r[nn] * v[nn].w;
        }
        p.x *= (1.f / 25.f); p.y *= (1.f / 25.f);
        p.z *= (1.f / 25.f); p.w *= (1.f / 25.f);

        auto layernorm = [&](float4& x) {
            float s1 = x.x + x.y + x.z + x.w;
            float s2 = x.x * x.x + x.y * x.y + x.z * x.z + x.w * x.w;
            warp_sum2(s1, s2);
            float mu = s1 * (1.f / MC_DIM);
            float ve = s2 * (1.f / MC_DIM) - mu * mu + 1e-5f;
            float rr = rsqrtf(ve);
            rr = rr * (1.5f - 0.5f * ve * rr * rr);
            x.x = (x.x - mu) * rr * g4.x + b4.x;
            x.y = (x.y - mu) * rr * g4.y + b4.y;
            x.z = (x.z - mu) * rr * g4.z + b4.z;
            x.w = (x.w - mu) * rr * g4.w + b4.w;
        };
        layernorm(p);

        const float scale = 0.08838834764831845f;   // 1/sqrt(128)
#pragma unroll
        for (int it = 1; it <= 2; it++) {
#pragma unroll
            for (int nn = 0; nn < N_ROUTES; nn++) {
                float d = v[nn].x * p.x + v[nn].y * p.y + v[nn].z * p.z + v[nn].w * p.w;
                d = warp_sum(d);
                if (lane == 0) s_agree[nn * KCLS + m] = d * scale;
            }
            __syncthreads();

            if (m < N_ROUTES) {
                float aval = (lane < KCLS) ? s_agree[m * KCLS + lane] : -1e30f;
                float mx = warp_max32(aval);
                float e = (lane < KCLS) ? expf(aval - mx) : 0.f;
                float s = warp_sum(e);
                if (lane < KCLS) s_coef[m * KCLS + lane] = e / s;
            }
            __syncthreads();

            if (it == 2 && tid < N_ROUTES * KCLS)
                out_coef[(size_t)r * (N_ROUTES * KCLS) + tid] = s_coef[tid];

            p = make_float4(0.f, 0.f, 0.f, 0.f);
#pragma unroll
            for (int nn = 0; nn < N_ROUTES; nn++) {
                float ca = s_coef[nn * KCLS + m] * a_r[nn];
                p.x += ca * v[nn].x;
                p.y += ca * v[nn].y;
                p.z += ca * v[nn].z;
                p.w += ca * v[nn].w;
            }
            layernorm(p);
            __syncthreads();
        }

        {
            float d = p.x * em.x + p.y * em.y + p.z * em.z + p.w * em.w;
            d = warp_sum(d);
            if (lane == 0) out_logits[(size_t)r * KCLS + m] = d + bi;
        }
        if (tid < N_ROUTES)
            out_act[(size_t)r * N_ROUTES + tid] = a_r[tid];

        buf ^= 1;
        __syncthreads();
    }
}

// ---------------------------------------------------------------------------
extern "C" void kernel_launch(void* const* d_in, const int* in_sizes, int n_in,
                              void* d_out, int out_size) {
    const float* prim_pose = (const float*)d_in[0];
    const float* prim_act  = (const float*)d_in[1];
    const float* w         = (const float*)d_in[2];
    const float* ln_gamma  = (const float*)d_in[3];
    const float* ln_beta   = (const float*)d_in[4];
    const float* embedding = (const float*)d_in[5];
    const float* bias      = (const float*)d_in[6];

    float* out        = (float*)d_out;
    float* out_logits = out;
    float* out_act    = out + (size_t)BSZ * KCLS;
    float* out_coef   = out_act + (size_t)BSZ * N_ROUTES;

    prep_p_kernel<<<(BSZ * PP_STRIDE) / 4 / 512, 512>>>(prim_pose);
    prep_w_kernel<<<dim3(COLS / 32, PC_DIM / 32, N_ROUTES), dim3(32, 8)>>>(w);

    cudaFuncSetAttribute(vote_gemm_tc,
                         cudaFuncAttributeMaxDynamicSharedMemorySize, GEMM_SMEM);
    dim3 g(COLS / 128, BSZ / 128, N_ROUTES);   // (25, 32, 7)
    vote_gemm_tc<<<g, 512, GEMM_SMEM>>>();

    cudaFuncSetAttribute(routing_kernel,
                         cudaFuncAttributeMaxDynamicSharedMemorySize, ROUT_SMEM);
    routing_kernel<<<ROUT_GRID, 800, ROUT_SMEM>>>(prim_act, ln_gamma, ln_beta,
                                                  embedding, bias,
                                                  out_logits, out_act, out_coef);
}

// round 13
// speedup vs baseline: 1.0734x; 1.0191x over previous
#include <cuda_runtime.h>
#include <cuda_fp16.h>
#include <stdint.h>
#include <math.h>

#define N_ROUTES 7
#define PC_DIM   512
#define MC_DIM   128
#define KCLS     25
#define BSZ      4096
#define COLS     (KCLS * MC_DIM)        // 3200
#define VOTE_PER_B (N_ROUTES * COLS)    // 22400
#define PP_STRIDE (N_ROUTES * PC_DIM)   // 3584

__device__ float g_vote[(size_t)BSZ * VOTE_PER_B];                    // 367 MB
__device__ __half g_Phi[(size_t)BSZ * PP_STRIDE];
__device__ __half g_Plo[(size_t)BSZ * PP_STRIDE];
__device__ __half g_Whi[(size_t)N_ROUTES * COLS * PC_DIM];            // [n][col][d]
__device__ __half g_Wlo[(size_t)N_ROUTES * COLS * PC_DIM];

__device__ __forceinline__ uint32_t smem_to_u32(const void* p) {
    uint32_t a;
    asm("{ .reg .u64 t; cvta.to.shared.u64 t, %1; cvt.u32.u64 %0, t; }"
        : "=r"(a) : "l"(p));
    return a;
}
__device__ __forceinline__ uint32_t usw64(uint32_t o) {     // SW64 swizzle
    return o ^ ((o >> 3) & 0x30);
}

#define CP_ASYNC(sa, ga) \
    asm volatile("cp.async.cg.shared.global [%0], [%1], 16;" :: "r"(sa), "l"(ga))
#define CP_COMMIT() asm volatile("cp.async.commit_group;" ::: "memory")
#define CP_WAIT(N)  asm volatile("cp.async.wait_group %0;" :: "n"(N))

// ---------------------------------------------------------------------------
// Prep 1: split prim_pose into fp16 hi/lo
// ---------------------------------------------------------------------------
__global__ __launch_bounds__(512) void prep_p_kernel(const float* __restrict__ P) {
    size_t i = (size_t)blockIdx.x * 512 + threadIdx.x;   // float4 index
    float4 x = ((const float4*)P)[i];
    __half h0 = __float2half(x.x), h1 = __float2half(x.y);
    __half h2 = __float2half(x.z), h3 = __float2half(x.w);
    __half2* dh = (__half2*)g_Phi;
    __half2* dl = (__half2*)g_Plo;
    dh[2 * i]     = __halves2half2(h0, h1);
    dh[2 * i + 1] = __halves2half2(h2, h3);
    dl[2 * i]     = __halves2half2(__float2half(x.x - __half2float(h0)),
                                   __float2half(x.y - __half2float(h1)));
    dl[2 * i + 1] = __halves2half2(__float2half(x.z - __half2float(h2)),
                                   __float2half(x.w - __half2float(h3)));
}

// ---------------------------------------------------------------------------
// Prep 2: transpose+split W[n][d][col] -> Whi/Wlo [n][col][d] (fp16)
// ---------------------------------------------------------------------------
__global__ __launch_bounds__(256) void prep_w_kernel(const float* __restrict__ W) {
    __shared__ float tile[32][33];
    const int n = blockIdx.z;
    const int c0 = blockIdx.x * 32;
    const int d0 = blockIdx.y * 32;
    const float* Wn = W + (size_t)n * PC_DIM * COLS;
#pragma unroll
    for (int j = 0; j < 4; j++) {
        int d = d0 + threadIdx.y + j * 8;
        tile[threadIdx.y + j * 8][threadIdx.x] = Wn[(size_t)d * COLS + c0 + threadIdx.x];
    }
    __syncthreads();
#pragma unroll
    for (int j = 0; j < 4; j++) {
        int col = c0 + threadIdx.y + j * 8;
        int d = d0 + threadIdx.x;
        float x = tile[threadIdx.x][threadIdx.y + j * 8];
        __half h = __float2half(x);
        size_t o = ((size_t)n * COLS + col) * PC_DIM + d;
        g_Whi[o] = h;
        g_Wlo[o] = __float2half(x - __half2float(h));
    }
}

// ---------------------------------------------------------------------------
// Vote GEMM: fp16 2-digit 3-term split (hh + hl + lh, all fp32 acc).
// CTA 128x128, 8 warps (4 wm x 2 wn, warp tile 32x64). KCH=32, SW64 smem,
// 3-stage cp.async. N-subtiles processed in PAIRS so each accumulator is
// re-touched at MMA distance 8 (covers HMMA RAW latency without relying on
// cross-warp interleave).
// ---------------------------------------------------------------------------
#define KCH 32
#define T_AH 0
#define T_AL 8192
#define T_BH 16384
#define T_BL 24576
#define STG_BYTES 32768
#define NSTG 3
#define GEMM_SMEM (NSTG * STG_BYTES)      // 98304 -> 2 CTAs/SM
#define NC (PC_DIM / KCH)                 // 16

#define LDSM_X4(r0, r1, r2, r3, a) \
    asm volatile("ldmatrix.sync.aligned.m8n8.x4.shared.b16 {%0,%1,%2,%3}, [%4];" \
        : "=r"(r0), "=r"(r1), "=r"(r2), "=r"(r3) : "r"(a))

#define MMA_F16(d, a, b0, b1) \
    asm volatile("mma.sync.aligned.m16n8k16.row.col.f32.f16.f16.f32 " \
        "{%0,%1,%2,%3}, {%4,%5,%6,%7}, {%8,%9}, {%0,%1,%2,%3};" \
        : "+f"((d)[0]), "+f"((d)[1]), "+f"((d)[2]), "+f"((d)[3]) \
        : "r"((a)[0]), "r"((a)[1]), "r"((a)[2]), "r"((a)[3]), "r"(b0), "r"(b1))

__global__ __launch_bounds__(256, 2) void vote_gemm_tc(void) {
    extern __shared__ char smem[];
    const uint32_t sb = smem_to_u32(smem);
    const int tid  = threadIdx.x;
    const int lane = tid & 31;
    const int warp = tid >> 5;
    const int wm   = warp & 3;          // M block of 32
    const int wn   = warp >> 2;         // N block of 64

    const int n  = blockIdx.z;
    const int bm = blockIdx.y * 128;
    const int bn = blockIdx.x * 128;

    const __half* Ahi = g_Phi + (size_t)bm * PP_STRIDE + (size_t)n * PC_DIM;
    const __half* Alo = g_Plo + (size_t)bm * PP_STRIDE + (size_t)n * PC_DIM;
    const __half* Bhi = g_Whi + ((size_t)n * COLS + bn) * PC_DIM;
    const __half* Blo = g_Wlo + ((size_t)n * COLS + bn) * PC_DIM;

    float acc[2][8][4];
#pragma unroll
    for (int i = 0; i < 2; i++)
#pragma unroll
        for (int j = 0; j < 8; j++)
#pragma unroll
            for (int q = 0; q < 4; q++) acc[i][j][q] = 0.f;

    const int lrow = lane & 15, lch = lane >> 4;

    auto issue_stage = [&](int c, int buf) {
        const int k0 = c * KCH;
        const uint32_t sbase = sb + buf * STG_BYTES;
#pragma unroll
        for (int p = 0; p < 8; p++) {
            int id  = p * 256 + tid;
            int t   = id >> 9;          // 0..3
            int rem = id & 511;
            int row = rem >> 2;
            int ch  = rem & 3;
            uint32_t sa = sbase + t * 8192 + usw64(row * 64 + ch * 16);
            const __half* g;
            if (t == 0)      g = Ahi + (size_t)row * PP_STRIDE + k0 + ch * 8;
            else if (t == 1) g = Alo + (size_t)row * PP_STRIDE + k0 + ch * 8;
            else if (t == 2) g = Bhi + (size_t)row * PC_DIM + k0 + ch * 8;
            else             g = Blo + (size_t)row * PC_DIM + k0 + ch * 8;
            CP_ASYNC(sa, g);
        }
        CP_COMMIT();
    };

    issue_stage(0, 0);
    issue_stage(1, 1);
    issue_stage(2, 2);

    for (int c = 0; c < NC; c++) {
        if (c <= NC - 3)      CP_WAIT(2);
        else if (c == NC - 2) CP_WAIT(1);
        else                  CP_WAIT(0);
        __syncthreads();

        const uint32_t sbase = sb + (c % 3) * STG_BYTES;
#pragma unroll
        for (int ks = 0; ks < 2; ks++) {
            const uint32_t kb = ks * 32 + lch * 16;
            uint32_t ah[2][4], al[2][4];
#pragma unroll
            for (int mt = 0; mt < 2; mt++) {
                uint32_t ao = usw64((wm * 32 + mt * 16 + lrow) * 64 + kb);
                LDSM_X4(ah[mt][0], ah[mt][1], ah[mt][2], ah[mt][3], sbase + T_AH + ao);
                LDSM_X4(al[mt][0], al[mt][1], al[mt][2], al[mt][3], sbase + T_AL + ao);
            }
#pragma unroll
            for (int gp = 0; gp < 4; gp += 2) {
                uint32_t bo0 = usw64((wn * 64 + gp * 16 + lrow) * 64 + kb);
                uint32_t bo1 = usw64((wn * 64 + (gp + 1) * 16 + lrow) * 64 + kb);
                uint32_t bh0[4], bl0[4], bh1[4], bl1[4];
                LDSM_X4(bh0[0], bh0[1], bh0[2], bh0[3], sbase + T_BH + bo0);
                LDSM_X4(bl0[0], bl0[1], bl0[2], bl0[3], sbase + T_BL + bo0);
                LDSM_X4(bh1[0], bh1[1], bh1[2], bh1[3], sbase + T_BH + bo1);
                LDSM_X4(bl1[0], bl1[1], bl1[2], bl1[3], sbase + T_BL + bo1);
                const int j0 = gp * 2;
                // ---- term hh (8 MMAs, all distinct accumulators) ----
                MMA_F16(acc[0][j0 + 0], ah[0], bh0[0], bh0[2]);
                MMA_F16(acc[0][j0 + 1], ah[0], bh0[1], bh0[3]);
                MMA_F16(acc[1][j0 + 0], ah[1], bh0[0], bh0[2]);
                MMA_F16(acc[1][j0 + 1], ah[1], bh0[1], bh0[3]);
                MMA_F16(acc[0][j0 + 2], ah[0], bh1[0], bh1[2]);
                MMA_F16(acc[0][j0 + 3], ah[0], bh1[1], bh1[3]);
                MMA_F16(acc[1][j0 + 2], ah[1], bh1[0], bh1[2]);
                MMA_F16(acc[1][j0 + 3], ah[1], bh1[1], bh1[3]);
                // ---- term hl (same accs, distance 8 from hh) ----
                MMA_F16(acc[0][j0 + 0], ah[0], bl0[0], bl0[2]);
                MMA_F16(acc[0][j0 + 1], ah[0], bl0[1], bl0[3]);
                MMA_F16(acc[1][j0 + 0], ah[1], bl0[0], bl0[2]);
                MMA_F16(acc[1][j0 + 1], ah[1], bl0[1], bl0[3]);
                MMA_F16(acc[0][j0 + 2], ah[0], bl1[0], bl1[2]);
                MMA_F16(acc[0][j0 + 3], ah[0], bl1[1], bl1[3]);
                MMA_F16(acc[1][j0 + 2], ah[1], bl1[0], bl1[2]);
                MMA_F16(acc[1][j0 + 3], ah[1], bl1[1], bl1[3]);
                // ---- term lh (distance 8 from hl) ----
                MMA_F16(acc[0][j0 + 0], al[0], bh0[0], bh0[2]);
                MMA_F16(acc[0][j0 + 1], al[0], bh0[1], bh0[3]);
                MMA_F16(acc[1][j0 + 0], al[1], bh0[0], bh0[2]);
                MMA_F16(acc[1][j0 + 1], al[1], bh0[1], bh0[3]);
                MMA_F16(acc[0][j0 + 2], al[0], bh1[0], bh1[2]);
                MMA_F16(acc[0][j0 + 3], al[0], bh1[1], bh1[3]);
                MMA_F16(acc[1][j0 + 2], al[1], bh1[0], bh1[2]);
                MMA_F16(acc[1][j0 + 3], al[1], bh1[1], bh1[3]);
            }
        }
        __syncthreads();
        if (c + 3 < NC) issue_stage(c + 3, (c + 3) % 3);
    }

    // epilogue: direct fp32 stores
#pragma unroll
    for (int mt = 0; mt < 2; mt++) {
#pragma unroll
        for (int j = 0; j < 8; j++) {
            int g = j >> 1, nt = j & 1;
            int row = bm + wm * 32 + mt * 16 + (lane >> 2);
            int col = bn + wn * 64 + g * 16 + nt * 8 + (lane & 3) * 2;
            float* d0 = g_vote + (size_t)row * VOTE_PER_B + (size_t)n * COLS + col;
            float* d1 = d0 + (size_t)8 * VOTE_PER_B;
            *(float2*)d0 = make_float2(acc[mt][j][0], acc[mt][j][1]);
            *(float2*)d1 = make_float2(acc[mt][j][2], acc[mt][j][3]);
        }
    }
}

// ---------------------------------------------------------------------------
// Persistent routing (R10, best known): 296 CTAs, 800 threads, double-buffered
// cp.async vote prefetch. Warp = capsule m.
// ---------------------------------------------------------------------------
#define ROUT_GRID 296
#define ROW_FLOATS VOTE_PER_B                    // 22400
#define ROUT_SMEM (2 * ROW_FLOATS * 4)           // 179200 bytes

__device__ __forceinline__ float warp_sum(float v) {
#pragma unroll
    for (int o = 16; o; o >>= 1) v += __shfl_xor_sync(0xffffffffu, v, o);
    return v;
}
__device__ __forceinline__ float warp_max32(float v) {
#pragma unroll
    for (int o = 16; o; o >>= 1) v = fmaxf(v, __shfl_xor_sync(0xffffffffu, v, o));
    return v;
}
__device__ __forceinline__ void warp_sum2(float& a, float& b) {
#pragma unroll
    for (int o = 16; o; o >>= 1) {
        a += __shfl_xor_sync(0xffffffffu, a, o);
        b += __shfl_xor_sync(0xffffffffu, b, o);
    }
}

__global__ __launch_bounds__(800, 1) void routing_kernel(
    const float* __restrict__ prim_act,
    const float* __restrict__ ln_gamma, const float* __restrict__ ln_beta,
    const float* __restrict__ embedding, const float* __restrict__ bias,
    float* __restrict__ out_logits, float* __restrict__ out_act,
    float* __restrict__ out_coef) {
    extern __shared__ float s_vote[];            // 2 x 22400 floats
    __shared__ float s_agree[N_ROUTES * KCLS];
    __shared__ float s_coef[N_ROUTES * KCLS];

    const int tid  = threadIdx.x;
    const int lane = tid & 31;
    const int m    = tid >> 5;                   // warp id == capsule, 0..24
    const uint32_t sb = smem_to_u32(s_vote);

    const float4 g4 = ((const float4*)ln_gamma)[lane];
    const float4 b4 = ((const float4*)ln_beta)[lane];
    const float4 em = ((const float4*)(embedding + (size_t)m * MC_DIM))[lane];
    const float  bi = bias[m];

    auto prefetch = [&](int row, int buf) {
        const float4* src = (const float4*)(g_vote + (size_t)row * VOTE_PER_B);
        const uint32_t dst = sb + buf * (ROW_FLOATS * 4);
#pragma unroll
        for (int j = 0; j < 7; j++) {
            int idx = tid + j * 800;             // 5600 float4 total
            CP_ASYNC(dst + idx * 16, src + idx);
        }
        CP_COMMIT();
    };

    prefetch(blockIdx.x, 0);
    int buf = 0;

    for (int r = blockIdx.x; r < BSZ; r += ROUT_GRID) {
        if (r + ROUT_GRID < BSZ) {
            prefetch(r + ROUT_GRID, buf ^ 1);
            CP_WAIT(1);
        } else {
            CP_WAIT(0);
        }
        __syncthreads();

        float a_r[N_ROUTES];
#pragma unroll
        for (int nn = 0; nn < N_ROUTES; nn++)
            a_r[nn] = prim_act[(size_t)r * N_ROUTES + nn];

        float4 v[N_ROUTES];
        {
            const float* vb = s_vote + buf * ROW_FLOATS + m * MC_DIM + lane * 4;
#pragma unroll
            for (int nn = 0; nn < N_ROUTES; nn++)
                v[nn] = *(const float4*)(vb + nn * COLS);
        }

        float4 p = make_float4(0.f, 0.f, 0.f, 0.f);
#pragma unroll
        for (int nn = 0; nn < N_ROUTES; nn++) {
            p.x += a_r[nn] * v[nn].x;
            p.y += a_r[nn] * v[nn].y;
            p.z += a_r[nn] * v[nn].z;
            p.w += a_r[nn] * v[nn].w;
        }
        p.x *= (1.f / 25.f); p.y *= (1.f / 25.f);
        p.z *= (1.f / 25.f); p.w *= (1.f / 25.f);

        auto layernorm = [&](float4& x) {
            float s1 = x.x + x.y + x.z + x.w;
            float s2 = x.x * x.x + x.y * x.y + x.z * x.z + x.w * x.w;
            warp_sum2(s1, s2);
            float mu = s1 * (1.f / MC_DIM);
            float ve = s2 * (1.f / MC_DIM) - mu * mu + 1e-5f;
            float rr = rsqrtf(ve);
            rr = rr * (1.5f - 0.5f * ve * rr * rr);
            x.x = (x.x - mu) * rr * g4.x + b4.x;
            x.y = (x.y - mu) * rr * g4.y + b4.y;
            x.z = (x.z - mu) * rr * g4.z + b4.z;
            x.w = (x.w - mu) * rr * g4.w + b4.w;
        };
        layernorm(p);

        const float scale = 0.08838834764831845f;   // 1/sqrt(128)
#pragma unroll
        for (int it = 1; it <= 2; it++) {
#pragma unroll
            for (int nn = 0; nn < N_ROUTES; nn++) {
                float d = v[nn].x * p.x + v[nn].y * p.y + v[nn].z * p.z + v[nn].w * p.w;
                d = warp_sum(d);
                if (lane == 0) s_agree[nn * KCLS + m] = d * scale;
            }
            __syncthreads();

            if (m < N_ROUTES) {
                float aval = (lane < KCLS) ? s_agree[m * KCLS + lane] : -1e30f;
                float mx = warp_max32(aval);
                float e = (lane < KCLS) ? expf(aval - mx) : 0.f;
                float s = warp_sum(e);
                if (lane < KCLS) s_coef[m * KCLS + lane] = e / s;
            }
            __syncthreads();

            if (it == 2 && tid < N_ROUTES * KCLS)
                out_coef[(size_t)r * (N_ROUTES * KCLS) + tid] = s_coef[tid];

            p = make_float4(0.f, 0.f, 0.f, 0.f);
#pragma unroll
            for (int nn = 0; nn < N_ROUTES; nn++) {
                float ca = s_coef[nn * KCLS + m] * a_r[nn];
                p.x += ca * v[nn].x;
                p.y += ca * v[nn].y;
                p.z += ca * v[nn].z;
                p.w += ca * v[nn].w;
            }
            layernorm(p);
            __syncthreads();
        }

        {
            float d = p.x * em.x + p.y * em.y + p.z * em.z + p.w * em.w;
            d = warp_sum(d);
            if (lane == 0) out_logits[(size_t)r * KCLS + m] = d + bi;
        }
        if (tid < N_ROUTES)
            out_act[(size_t)r * N_ROUTES + tid] = a_r[tid];

        buf ^= 1;
        __syncthreads();
    }
}

// ---------------------------------------------------------------------------
extern "C" void kernel_launch(void* const* d_in, const int* in_sizes, int n_in,
                              void* d_out, int out_size) {
    const float* prim_pose = (const float*)d_in[0];
    const float* prim_act  = (const float*)d_in[1];
    const float* w         = (const float*)d_in[2];
    const float* ln_gamma  = (const float*)d_in[3];
    const float* ln_beta   = (const float*)d_in[4];
    const float* embedding = (const float*)d_in[5];
    const float* bias      = (const float*)d_in[6];

    float* out        = (float*)d_out;
    float* out_logits = out;
    float* out_act    = out + (size_t)BSZ * KCLS;
    float* out_coef   = out_act + (size_t)BSZ * N_ROUTES;

    prep_p_kernel<<<(BSZ * PP_STRIDE) / 4 / 512, 512>>>(prim_pose);
    prep_w_kernel<<<dim3(COLS / 32, PC_DIM / 32, N_ROUTES), dim3(32, 8)>>>(w);

    cudaFuncSetAttribute(vote_gemm_tc,
                         cudaFuncAttributeMaxDynamicSharedMemorySize, GEMM_SMEM);
    dim3 g(COLS / 128, BSZ / 128, N_ROUTES);   // (25, 32, 7)
    vote_gemm_tc<<<g, 256, GEMM_SMEM>>>();

    cudaFuncSetAttribute(routing_kernel,
                         cudaFuncAttributeMaxDynamicSharedMemorySize, ROUT_SMEM);
    routing_kernel<<<ROUT_GRID, 800, ROUT_SMEM>>>(prim_act, ln_gamma, ln_beta,
                                                  embedding, bias,
                                                  out_logits, out_act, out_coef);
}